// round 1
// baseline (speedup 1.0000x reference)
#include <cuda_runtime.h>

#define HW   4096
#define NB   4
#define CIN  256
#define DQK  64
#define BQ   64
#define BK   64

// Scratch (static device globals: allocation-free per harness rules)
__device__ float Qg[NB * HW * DQK];   // [b][i][k]  4 MB
__device__ float Kg[NB * HW * DQK];   // [b][j][k]  4 MB
__device__ float Vg[NB * HW * CIN];   // [b][j][c] 16 MB

// ---- packed f32x2 helpers (Blackwell FFMA2) ----
__device__ __forceinline__ unsigned long long pk2(float a, float b) {
    unsigned long long r;
    asm("mov.b64 %0, {%1, %2};" : "=l"(r) : "r"(__float_as_int(a)), "r"(__float_as_int(b)));
    return r;
}
__device__ __forceinline__ void upk2(unsigned long long v, float& a, float& b) {
    int x, y;
    asm("mov.b64 {%0, %1}, %2;" : "=r"(x), "=r"(y) : "l"(v));
    a = __int_as_float(x); b = __int_as_float(y);
}
__device__ __forceinline__ void ffma2(unsigned long long& d, unsigned long long a, unsigned long long b) {
    asm("fma.rn.f32x2 %0, %1, %2, %0;" : "+l"(d) : "l"(a), "l"(b));
}

// ============================================================
// Projection kernel: 1x1 convs -> Qg/Kg/Vg
// grid (16, NB, 6): z=0 -> Q, z=1 -> K, z=2..5 -> V chunk of 64 channels
// ============================================================
__global__ __launch_bounds__(256) void proj_kernel(
    const float* __restrict__ src, const float* __restrict__ ref,
    const float* __restrict__ w_src, const float* __restrict__ b_src,
    const float* __restrict__ w_ref, const float* __restrict__ b_ref,
    const float* __restrict__ w_gate, const float* __restrict__ b_gate)
{
    __shared__ float Wsm[128][66];   // half of the 64x256 weight chunk, transposed

    const int z = blockIdx.z;
    const int b = blockIdx.y;
    const int i = blockIdx.x * 256 + threadIdx.x;

    const float *X, *W, *bias;
    if (z == 0)      { X = src; W = w_src;                     bias = b_src; }
    else if (z == 1) { X = ref; W = w_ref;                     bias = b_ref; }
    else             { X = ref; W = w_gate + (z - 2) * 64 * CIN; bias = b_gate + (z - 2) * 64; }

    unsigned long long acc2[32];
    #pragma unroll
    for (int o = 0; o < 32; o++) acc2[o] = pk2(bias[2 * o], bias[2 * o + 1]);

    const float* Xp = X + (size_t)b * CIN * HW + i;

    for (int half = 0; half < 2; half++) {
        __syncthreads();
        // stage W[o][half*128 + c] -> Wsm[c][o]   (gmem-coalesced over c)
        for (int t = threadIdx.x; t < 64 * 128; t += 256) {
            int o = t >> 7;          // 0..63
            int c = t & 127;         // 0..127
            Wsm[c][o] = W[o * CIN + half * 128 + c];
        }
        __syncthreads();
        #pragma unroll 4
        for (int c = 0; c < 128; c++) {
            float x = Xp[(half * 128 + c) * HW];
            unsigned long long xx = pk2(x, x);
            const unsigned long long* wr = (const unsigned long long*)&Wsm[c][0];
            #pragma unroll
            for (int o = 0; o < 32; o++) ffma2(acc2[o], wr[o], xx);
        }
    }

    float* outp;
    if (z == 0)      outp = Qg + ((size_t)b * HW + i) * DQK;
    else if (z == 1) outp = Kg + ((size_t)b * HW + i) * DQK;
    else             outp = Vg + ((size_t)b * HW + i) * CIN + (z - 2) * 64;

    #pragma unroll
    for (int o = 0; o < 32; o++) {
        float a, bb; upk2(acc2[o], a, bb);
        outp[2 * o]     = a;
        outp[2 * o + 1] = bb;
    }
}

// ============================================================
// Fused flash-style attention + epilogue
//   grid (HW/BQ, NB), 256 threads, dynamic smem
// smem layout (floats):
//   Qts [64][68] @ 0        (k-major, transposed)
//   Kts [64][68] @ 4352
//   Vs  [64][256] @ 8704
//   Ps  [64][65] @ 25088
// total 29248 floats = 116992 bytes
// ============================================================
#define QTS_OFF 0
#define KTS_OFF 4352
#define VS_OFF  8704
#define PS_OFF  25088
#define ATTN_SMEM_BYTES (29248 * 4)

__global__ __launch_bounds__(256, 1) void attn_kernel(
    const float* __restrict__ srcf, const float* __restrict__ gammap,
    float* __restrict__ out)
{
    extern __shared__ float sm[];
    const int b   = blockIdx.y;
    const int q0  = blockIdx.x * BQ;
    const int tid = threadIdx.x;

    // load Q tile transposed: Qts[kk][qi]
    const float* Qp = Qg + ((size_t)b * HW + q0) * DQK;
    for (int t = tid; t < BQ * DQK; t += 256) {
        int qi = t >> 6, kk = t & 63;
        sm[QTS_OFF + kk * 68 + qi] = Qp[qi * DQK + kk];
    }

    unsigned long long acc2[32];
    #pragma unroll
    for (int c = 0; c < 32; c++) acc2[c] = 0ULL;
    float den = 0.f;

    const int qb = (tid >> 4) * 4;   // S-phase: 16x16 grid of 4x4 tiles
    const int kb = (tid & 15) * 4;
    const int qi = tid & 63;         // PV-phase: 4 threads per query
    const int g  = tid >> 6;

    const float* Kp = Kg + (size_t)b * HW * DQK;
    const float* Vp = Vg + (size_t)b * HW * CIN;

    for (int j0 = 0; j0 < HW; j0 += BK) {
        __syncthreads();   // prev iter's PV done before overwriting tiles

        // K tile transposed: Kts[kk][jl]
        for (int t = tid; t < BK * DQK; t += 256) {
            int jl = t >> 6, kk = t & 63;
            sm[KTS_OFF + kk * 68 + jl] = Kp[(size_t)(j0 + jl) * DQK + kk];
        }
        // V tile: Vs[jl][c], float4 copies
        for (int t = tid; t < BK * (CIN / 4); t += 256) {
            int jl = t >> 6, c4 = t & 63;
            *(float4*)&sm[VS_OFF + jl * 256 + c4 * 4] =
                *(const float4*)&Vp[(size_t)(j0 + jl) * CIN + c4 * 4];
        }
        __syncthreads();

        // ---- S = Q K^T (4x4 per thread) ----
        float s[4][4];
        #pragma unroll
        for (int a = 0; a < 4; a++)
            #pragma unroll
            for (int bb = 0; bb < 4; bb++) s[a][bb] = 0.f;

        #pragma unroll 8
        for (int kk = 0; kk < DQK; kk++) {
            float4 qv = *(const float4*)&sm[QTS_OFF + kk * 68 + qb];
            float4 kv = *(const float4*)&sm[KTS_OFF + kk * 68 + kb];
            s[0][0] = fmaf(qv.x, kv.x, s[0][0]);
            s[0][1] = fmaf(qv.x, kv.y, s[0][1]);
            s[0][2] = fmaf(qv.x, kv.z, s[0][2]);
            s[0][3] = fmaf(qv.x, kv.w, s[0][3]);
            s[1][0] = fmaf(qv.y, kv.x, s[1][0]);
            s[1][1] = fmaf(qv.y, kv.y, s[1][1]);
            s[1][2] = fmaf(qv.y, kv.z, s[1][2]);
            s[1][3] = fmaf(qv.y, kv.w, s[1][3]);
            s[2][0] = fmaf(qv.z, kv.x, s[2][0]);
            s[2][1] = fmaf(qv.z, kv.y, s[2][1]);
            s[2][2] = fmaf(qv.z, kv.z, s[2][2]);
            s[2][3] = fmaf(qv.z, kv.w, s[2][3]);
            s[3][0] = fmaf(qv.w, kv.x, s[3][0]);
            s[3][1] = fmaf(qv.w, kv.y, s[3][1]);
            s[3][2] = fmaf(qv.w, kv.z, s[3][2]);
            s[3][3] = fmaf(qv.w, kv.w, s[3][3]);
        }

        // P = exp(S/16). Logits are tiny (|s/16| < ~10) -> no max-subtraction
        // needed; softmax is shift-invariant so result is exact.
        #pragma unroll
        for (int iq = 0; iq < 4; iq++)
            #pragma unroll
            for (int ik = 0; ik < 4; ik++)
                sm[PS_OFF + (qb + iq) * 65 + (kb + ik)] = __expf(s[iq][ik] * 0.0625f);
        __syncthreads();

        // ---- acc += P @ V  (packed f32x2), den += sum_j P ----
        #pragma unroll 2
        for (int j = 0; j < BK; j++) {
            float p = sm[PS_OFF + qi * 65 + j];
            den += p;
            unsigned long long pp = pk2(p, p);
            const ulonglong2* v2 = (const ulonglong2*)&sm[VS_OFF + j * 256 + g * 64];
            #pragma unroll
            for (int c = 0; c < 16; c++) {
                ulonglong2 v = v2[c];
                ffma2(acc2[2 * c],     v.x, pp);
                ffma2(acc2[2 * c + 1], v.y, pp);
            }
        }
    }

    // ---- epilogue: out = gamma * acc/den + src ----
    const float gamma = __ldg(gammap);
    const float scl   = gamma / den;
    const float* sp = srcf + (size_t)b * CIN * HW;
    float*       op = out  + (size_t)b * CIN * HW;
    const int i = q0 + qi;

    #pragma unroll
    for (int c = 0; c < 32; c++) {
        float a, bb; upk2(acc2[c], a, bb);
        int ch0 = g * 64 + 2 * c;
        op[(size_t)ch0 * HW + i]       = fmaf(a,  scl, sp[(size_t)ch0 * HW + i]);
        op[(size_t)(ch0 + 1) * HW + i] = fmaf(bb, scl, sp[(size_t)(ch0 + 1) * HW + i]);
    }
}

// ============================================================
extern "C" void kernel_launch(void* const* d_in, const int* in_sizes, int n_in,
                              void* d_out, int out_size)
{
    const float* src    = (const float*)d_in[0];
    const float* ref    = (const float*)d_in[1];
    const float* w_src  = (const float*)d_in[2];
    const float* b_src  = (const float*)d_in[3];
    const float* w_ref  = (const float*)d_in[4];
    const float* b_ref  = (const float*)d_in[5];
    const float* w_gate = (const float*)d_in[6];
    const float* b_gate = (const float*)d_in[7];
    const float* gamma  = (const float*)d_in[8];
    float* out = (float*)d_out;

    // opt-in to >48KB dynamic smem (idempotent, capture-safe host call)
    cudaFuncSetAttribute(attn_kernel, cudaFuncAttributeMaxDynamicSharedMemorySize,
                         ATTN_SMEM_BYTES);

    proj_kernel<<<dim3(HW / 256, NB, 6), 256>>>(src, ref, w_src, b_src,
                                                w_ref, b_ref, w_gate, b_gate);
    attn_kernel<<<dim3(HW / BQ, NB), 256, ATTN_SMEM_BYTES>>>(src, gamma, out);
}

// round 5
// speedup vs baseline: 2.0984x; 2.0984x over previous
#include <cuda_runtime.h>
#include <cuda_bf16.h>
#include <cstdint>

#define HW   4096
#define NB   4
#define CIN  256
#define DQK  64
#define BQ   64           // queries per CTA
#define BK   64           // keys per iteration
#define NITER (HW / BK)   // 64

// ---------------- scratch (bf16) ----------------
__device__ __nv_bfloat16 Qg[NB * HW * DQK];        // [b][i][k]   2 MB
__device__ __nv_bfloat16 Kg[NB * HW * DQK];        // [b][j][k]   2 MB
__device__ __nv_bfloat16 Vtg[NB * CIN * HW];       // [b][c][j]   8 MB (channel-major)

// ---------------- helpers ----------------
__device__ __forceinline__ uint32_t smem_u32(const void* p) {
    uint32_t a;
    asm("{ .reg .u64 t; cvta.to.shared.u64 t, %1; cvt.u32.u64 %0, t; }" : "=r"(a) : "l"(p));
    return a;
}
__device__ __forceinline__ void cp_async16(uint32_t dst, const void* src) {
    asm volatile("cp.async.cg.shared.global [%0], [%1], 16;" :: "r"(dst), "l"(src));
}
#define CP_COMMIT() asm volatile("cp.async.commit_group;" ::: "memory")

__device__ __forceinline__ uint32_t lds_b32(uint32_t a) {
    uint32_t v;
    asm volatile("ld.shared.b32 %0, [%1];" : "=r"(v) : "r"(a));
    return v;
}
__device__ __forceinline__ uint32_t cvt_bf16x2(float lo, float hi) {
    uint32_t r;
    asm("cvt.rn.bf16x2.f32 %0, %1, %2;" : "=r"(r) : "f"(hi), "f"(lo));
    return r;
}
// D += A(16x16,row) * B(16x8,col)  bf16 -> f32
__device__ __forceinline__ void mma16816(float& c0, float& c1, float& c2, float& c3,
                                         uint32_t a0, uint32_t a1, uint32_t a2, uint32_t a3,
                                         uint32_t b0, uint32_t b1) {
    asm volatile(
        "mma.sync.aligned.m16n8k16.row.col.f32.bf16.bf16.f32 "
        "{%0,%1,%2,%3}, {%4,%5,%6,%7}, {%8,%9}, {%0,%1,%2,%3};"
        : "+f"(c0), "+f"(c1), "+f"(c2), "+f"(c3)
        : "r"(a0), "r"(a1), "r"(a2), "r"(a3), "r"(b0), "r"(b1));
}

// packed f32x2 (projection kernel)
__device__ __forceinline__ unsigned long long pk2(float a, float b) {
    unsigned long long r;
    asm("mov.b64 %0, {%1, %2};" : "=l"(r) : "r"(__float_as_int(a)), "r"(__float_as_int(b)));
    return r;
}
__device__ __forceinline__ void upk2(unsigned long long v, float& a, float& b) {
    int x, y;
    asm("mov.b64 {%0, %1}, %2;" : "=r"(x), "=r"(y) : "l"(v));
    a = __int_as_float(x); b = __int_as_float(y);
}
__device__ __forceinline__ void ffma2(unsigned long long& d, unsigned long long a, unsigned long long b) {
    asm("fma.rn.f32x2 %0, %1, %2, %0;" : "+l"(d) : "l"(a), "l"(b));
}

// ---------------- SMEM layout (bytes) ----------------
// padded rows: 72 halves = 144 B per logical 64-half row
#define SM_Q    0                  // 64 x 144       =  9216
#define SM_K0   9216               // 64 x 144       =  9216
#define SM_K1   18432
#define SM_V0   27648              // 256 x 144      = 36864
#define SM_V1   64512
#define SM_TOTAL 101376
#define SM_STG  9216               // epilogue staging (reuses K bufs): 64*68*4 = 17408
#define KROW    144
#define VROW    144

// ============================================================
// Projection kernel (fp32 math, bf16 outputs; V written channel-major)
// grid (16, NB, 6): z=0->Q, z=1->K, z=2..5 -> V channels (z-2)*64..+63
// ============================================================
__global__ __launch_bounds__(256) void proj_kernel(
    const float* __restrict__ src, const float* __restrict__ ref,
    const float* __restrict__ w_src, const float* __restrict__ b_src,
    const float* __restrict__ w_ref, const float* __restrict__ b_ref,
    const float* __restrict__ w_gate, const float* __restrict__ b_gate)
{
    __shared__ float Wsm[128][66];

    const int z = blockIdx.z;
    const int b = blockIdx.y;
    const int i = blockIdx.x * 256 + threadIdx.x;

    const float *X, *W, *bias;
    if (z == 0)      { X = src; W = w_src;                       bias = b_src; }
    else if (z == 1) { X = ref; W = w_ref;                       bias = b_ref; }
    else             { X = ref; W = w_gate + (z - 2) * 64 * CIN; bias = b_gate + (z - 2) * 64; }

    unsigned long long acc2[32];
    #pragma unroll
    for (int o = 0; o < 32; o++) acc2[o] = pk2(bias[2 * o], bias[2 * o + 1]);

    const float* Xp = X + (size_t)b * CIN * HW + i;

    for (int half = 0; half < 2; half++) {
        __syncthreads();
        for (int t = threadIdx.x; t < 64 * 128; t += 256) {
            int o = t >> 7, c = t & 127;
            Wsm[c][o] = W[o * CIN + half * 128 + c];
        }
        __syncthreads();
        #pragma unroll 4
        for (int c = 0; c < 128; c++) {
            float x = Xp[(half * 128 + c) * HW];
            unsigned long long xx = pk2(x, x);
            const unsigned long long* wr = (const unsigned long long*)&Wsm[c][0];
            #pragma unroll
            for (int o = 0; o < 32; o++) ffma2(acc2[o], wr[o], xx);
        }
    }

    if (z == 0 || z == 1) {
        __nv_bfloat16* outp = (z == 0 ? Qg : Kg) + ((size_t)b * HW + i) * DQK;
        #pragma unroll
        for (int o = 0; o < 32; o++) {
            float a, bb; upk2(acc2[o], a, bb);
            outp[2 * o]     = __float2bfloat16(a);
            outp[2 * o + 1] = __float2bfloat16(bb);
        }
    } else {
        const int ch0 = (z - 2) * 64;
        #pragma unroll
        for (int o = 0; o < 32; o++) {
            float a, bb; upk2(acc2[o], a, bb);
            Vtg[((size_t)(b * CIN + ch0 + 2 * o))     * HW + i] = __float2bfloat16(a);
            Vtg[((size_t)(b * CIN + ch0 + 2 * o + 1)) * HW + i] = __float2bfloat16(bb);
        }
    }
}

// ============================================================
// bf16 HMMA flash attention + epilogue. grid (HW/BQ=64, NB), 128 threads.
// Each warp: 16 query rows x 256 channels.
// ============================================================
__device__ __forceinline__ void issue_kv(uint32_t sb, int koff, int voff,
                                         int b, int j0, int tid)
{
    // K tile: 64 rows x 128B (8 x 16B chunks), padded stride 144B
    const __nv_bfloat16* kp = Kg + ((size_t)b * HW + j0) * DQK;
    #pragma unroll
    for (int t = tid; t < 64 * 8; t += 128) {
        int r = t >> 3, c8 = t & 7;
        cp_async16(sb + koff + r * KROW + c8 * 16, kp + r * DQK + c8 * 8);
    }
    // V tile: 256 channel rows x 128B
    #pragma unroll
    for (int t = tid; t < 256 * 8; t += 128) {
        int c = t >> 3, c8 = t & 7;
        cp_async16(sb + voff + c * VROW + c8 * 16,
                   Vtg + ((size_t)(b * CIN + c)) * HW + j0 + c8 * 8);
    }
}

__global__ __launch_bounds__(128, 2) void attn_kernel(
    const float* __restrict__ srcf, const float* __restrict__ gammap,
    float* __restrict__ out)
{
    extern __shared__ char smem[];
    const uint32_t sb = smem_u32(smem);
    const int tid  = threadIdx.x;
    const int warp = tid >> 5;
    const int lane = tid & 31;
    const int b    = blockIdx.y;
    const int q0   = blockIdx.x * BQ;
    const int qr   = (lane >> 2);        // row-in-tile 0..7
    const int m4   = (lane & 3);         // quad col

    // prologue: Q (group 0), K0/V0 (group 1)
    {
        const __nv_bfloat16* qp = Qg + ((size_t)b * HW + q0) * DQK;
        #pragma unroll
        for (int t = tid; t < 64 * 8; t += 128) {
            int r = t >> 3, c8 = t & 7;
            cp_async16(sb + SM_Q + r * KROW + c8 * 16, qp + r * DQK + c8 * 8);
        }
        CP_COMMIT();
        issue_kv(sb, SM_K0, SM_V0, b, 0, tid);
        CP_COMMIT();
    }

    float oacc[128];
    #pragma unroll
    for (int i = 0; i < 128; i++) oacc[i] = 0.f;
    float den0 = 0.f, den1 = 0.f;
    uint32_t aq[4][4];

    const float SCL = 0.0625f * 1.44269504088896f;   // (1/16) * log2(e)

    #pragma unroll 1
    for (int j = 0; j < NITER; j++) {
        const int koff = (j & 1) ? SM_K1 : SM_K0;
        const int voff = (j & 1) ? SM_V1 : SM_V0;

        if (j + 1 < NITER) {
            issue_kv(sb, (j & 1) ? SM_K0 : SM_K1, (j & 1) ? SM_V0 : SM_V1,
                     b, (j + 1) * BK, tid);
            CP_COMMIT();
            asm volatile("cp.async.wait_group 1;" ::: "memory");
        } else {
            asm volatile("cp.async.wait_group 0;" ::: "memory");
        }
        __syncthreads();

        if (j == 0) {
            // Q A-frags, once: rows warp*16 + qr (+8), k-steps 0..3
            const uint32_t qbase = sb + SM_Q + (warp * 16 + qr) * KROW + m4 * 4;
            #pragma unroll
            for (int ks = 0; ks < 4; ks++) {
                aq[ks][0] = lds_b32(qbase + ks * 32);
                aq[ks][1] = lds_b32(qbase + 8 * KROW + ks * 32);
                aq[ks][2] = lds_b32(qbase + ks * 32 + 16);
                aq[ks][3] = lds_b32(qbase + 8 * KROW + ks * 32 + 16);
            }
        }

        // ---- S = Q K^T : 8 n-tiles (64 keys) ----
        float s[8][4];
        #pragma unroll
        for (int nt = 0; nt < 8; nt++)
            #pragma unroll
            for (int c = 0; c < 4; c++) s[nt][c] = 0.f;

        #pragma unroll
        for (int ks = 0; ks < 4; ks++) {
            const uint32_t kb = sb + koff + qr * KROW + ks * 32 + m4 * 4;
            #pragma unroll
            for (int nt = 0; nt < 8; nt++) {
                uint32_t b0 = lds_b32(kb + nt * 8 * KROW);
                uint32_t b1 = lds_b32(kb + nt * 8 * KROW + 16);
                mma16816(s[nt][0], s[nt][1], s[nt][2], s[nt][3],
                         aq[ks][0], aq[ks][1], aq[ks][2], aq[ks][3], b0, b1);
            }
        }

        // ---- P = exp2(S * SCL), pack to bf16 A-frags, accumulate den ----
        uint32_t pa[4][4];
        #pragma unroll
        for (int ks = 0; ks < 4; ks++) {
            float e0a = exp2f(s[2 * ks][0] * SCL);
            float e1a = exp2f(s[2 * ks][1] * SCL);
            float e2a = exp2f(s[2 * ks][2] * SCL);
            float e3a = exp2f(s[2 * ks][3] * SCL);
            float e0b = exp2f(s[2 * ks + 1][0] * SCL);
            float e1b = exp2f(s[2 * ks + 1][1] * SCL);
            float e2b = exp2f(s[2 * ks + 1][2] * SCL);
            float e3b = exp2f(s[2 * ks + 1][3] * SCL);
            den0 += e0a + e1a + e0b + e1b;
            den1 += e2a + e3a + e2b + e3b;
            pa[ks][0] = cvt_bf16x2(e0a, e1a);
            pa[ks][1] = cvt_bf16x2(e2a, e3a);
            pa[ks][2] = cvt_bf16x2(e0b, e1b);
            pa[ks][3] = cvt_bf16x2(e2b, e3b);
        }

        // ---- O += P V^T : 32 channel n-tiles ----
        #pragma unroll
        for (int ks = 0; ks < 4; ks++) {
            const uint32_t vb = sb + voff + qr * VROW + ks * 32 + m4 * 4;
            #pragma unroll
            for (int nt = 0; nt < 32; nt++) {
                uint32_t b0 = lds_b32(vb + nt * 8 * VROW);
                uint32_t b1 = lds_b32(vb + nt * 8 * VROW + 16);
                mma16816(oacc[nt * 4 + 0], oacc[nt * 4 + 1],
                         oacc[nt * 4 + 2], oacc[nt * 4 + 3],
                         pa[ks][0], pa[ks][1], pa[ks][2], pa[ks][3], b0, b1);
            }
        }
        __syncthreads();   // done with this buffer before it is refilled
    }

    // ---- den reduction across quad (cols) ----
    den0 += __shfl_xor_sync(0xffffffffu, den0, 1);
    den0 += __shfl_xor_sync(0xffffffffu, den0, 2);
    den1 += __shfl_xor_sync(0xffffffffu, den1, 1);
    den1 += __shfl_xor_sync(0xffffffffu, den1, 2);
    const float gamma = __ldg(gammap);
    const float s0 = gamma / den0;
    const float s1 = gamma / den1;

    // ---- epilogue: stage 64-channel chunks in SMEM, coalesced out ----
    float* stg = (float*)(smem + SM_STG);     // [64 ch][68] floats
    const float* sp = srcf + (size_t)b * CIN * HW;
    float*       op = out  + (size_t)b * CIN * HW;
    const int qloc = warp * 16 + qr;

    #pragma unroll 1
    for (int cc = 0; cc < 4; cc++) {
        __syncthreads();
        #pragma unroll
        for (int nt8 = 0; nt8 < 8; nt8++) {
            int nt = cc * 8 + nt8;
            int ch = nt8 * 8 + 2 * m4;
            stg[ch * 68 + qloc]           = oacc[nt * 4 + 0] * s0;
            stg[(ch + 1) * 68 + qloc]     = oacc[nt * 4 + 1] * s0;
            stg[ch * 68 + qloc + 8]       = oacc[nt * 4 + 2] * s1;
            stg[(ch + 1) * 68 + qloc + 8] = oacc[nt * 4 + 3] * s1;
        }
        __syncthreads();
        #pragma unroll
        for (int idx = tid; idx < 64 * 64; idx += 128) {
            int ch = idx >> 6, q = idx & 63;
            size_t g = (size_t)(cc * 64 + ch) * HW + q0 + q;
            op[g] = stg[ch * 68 + q] + sp[g];
        }
    }
}

// ============================================================
extern "C" void kernel_launch(void* const* d_in, const int* in_sizes, int n_in,
                              void* d_out, int out_size)
{
    const float* src    = (const float*)d_in[0];
    const float* ref    = (const float*)d_in[1];
    const float* w_src  = (const float*)d_in[2];
    const float* b_src  = (const float*)d_in[3];
    const float* w_ref  = (const float*)d_in[4];
    const float* b_ref  = (const float*)d_in[5];
    const float* w_gate = (const float*)d_in[6];
    const float* b_gate = (const float*)d_in[7];
    const float* gamma  = (const float*)d_in[8];
    float* out = (float*)d_out;

    cudaFuncSetAttribute(attn_kernel, cudaFuncAttributeMaxDynamicSharedMemorySize,
                         SM_TOTAL);

    proj_kernel<<<dim3(HW / 256, NB, 6), 256>>>(src, ref, w_src, b_src,
                                                w_ref, b_ref, w_gate, b_gate);
    attn_kernel<<<dim3(HW / BQ, NB), 128, SM_TOTAL>>>(src, gamma, out);
}

// round 6
// speedup vs baseline: 4.2044x; 2.0036x over previous
#include <cuda_runtime.h>
#include <cuda_bf16.h>
#include <cstdint>

#define HW   4096
#define NB   4
#define CIN  256
#define DQK  64
#define BQ   64           // queries per CTA
#define BK   64           // keys per iteration
#define NITER (HW / BK)   // 64
#define CHPC 128          // channels per CTA (z-split)

// ---------------- scratch (bf16) ----------------
__device__ __nv_bfloat16 Qg[NB * HW * DQK];        // [b][i][k]   2 MB
__device__ __nv_bfloat16 Kg[NB * HW * DQK];        // [b][j][k]   2 MB
__device__ __nv_bfloat16 Vtg[NB * CIN * HW];       // [b][c][j]   8 MB (channel-major)

// ---------------- helpers ----------------
__device__ __forceinline__ uint32_t smem_u32(const void* p) {
    uint32_t a;
    asm("{ .reg .u64 t; cvta.to.shared.u64 t, %1; cvt.u32.u64 %0, t; }" : "=r"(a) : "l"(p));
    return a;
}
__device__ __forceinline__ void cp_async16(uint32_t dst, const void* src) {
    asm volatile("cp.async.cg.shared.global [%0], [%1], 16;" :: "r"(dst), "l"(src));
}
#define CP_COMMIT() asm volatile("cp.async.commit_group;" ::: "memory")

__device__ __forceinline__ uint32_t lds_b32(uint32_t a) {
    uint32_t v;
    asm volatile("ld.shared.b32 %0, [%1];" : "=r"(v) : "r"(a));
    return v;
}
__device__ __forceinline__ void ldmx4(uint32_t& r0, uint32_t& r1, uint32_t& r2, uint32_t& r3,
                                      uint32_t a) {
    asm volatile("ldmatrix.sync.aligned.m8n8.x4.shared.b16 {%0,%1,%2,%3}, [%4];"
                 : "=r"(r0), "=r"(r1), "=r"(r2), "=r"(r3) : "r"(a));
}
__device__ __forceinline__ uint32_t cvt_bf16x2(float lo, float hi) {
    uint32_t r;
    asm("cvt.rn.bf16x2.f32 %0, %1, %2;" : "=r"(r) : "f"(hi), "f"(lo));
    return r;
}
// D += A(16x16,row) * B(16x8,col)  bf16 -> f32
__device__ __forceinline__ void mma16816(float& c0, float& c1, float& c2, float& c3,
                                         uint32_t a0, uint32_t a1, uint32_t a2, uint32_t a3,
                                         uint32_t b0, uint32_t b1) {
    asm volatile(
        "mma.sync.aligned.m16n8k16.row.col.f32.bf16.bf16.f32 "
        "{%0,%1,%2,%3}, {%4,%5,%6,%7}, {%8,%9}, {%0,%1,%2,%3};"
        : "+f"(c0), "+f"(c1), "+f"(c2), "+f"(c3)
        : "r"(a0), "r"(a1), "r"(a2), "r"(a3), "r"(b0), "r"(b1));
}

// packed f32x2 (projection kernel)
__device__ __forceinline__ unsigned long long pk2(float a, float b) {
    unsigned long long r;
    asm("mov.b64 %0, {%1, %2};" : "=l"(r) : "r"(__float_as_int(a)), "r"(__float_as_int(b)));
    return r;
}
__device__ __forceinline__ void upk2(unsigned long long v, float& a, float& b) {
    int x, y;
    asm("mov.b64 {%0, %1}, %2;" : "=r"(x), "=r"(y) : "l"(v));
    a = __int_as_float(x); b = __int_as_float(y);
}
__device__ __forceinline__ void ffma2(unsigned long long& d, unsigned long long a, unsigned long long b) {
    asm("fma.rn.f32x2 %0, %1, %2, %0;" : "+l"(d) : "l"(a), "l"(b));
}

// ---------------- SMEM layout (bytes) ----------------
// padded rows: 72 halves = 144 B per logical 64-half row (9 x 16B: ldmatrix conflict-free)
#define KROW    144
#define VROW    144
#define SM_Q    0                  // 64  x 144 =  9216
#define SM_K0   9216               // 64  x 144 =  9216
#define SM_K1   18432
#define SM_V0   27648              // 128 x 144 = 18432
#define SM_V1   46080
#define SM_TOTAL 64512
#define SM_STG  9216               // epilogue staging (reuses K bufs): 64*68*4 = 17408

// ============================================================
// Projection kernel (fp32 math, bf16 outputs; V written channel-major)
// grid (16, NB, 6): z=0->Q, z=1->K, z=2..5 -> V channels (z-2)*64..+63
// ============================================================
__global__ __launch_bounds__(256) void proj_kernel(
    const float* __restrict__ src, const float* __restrict__ ref,
    const float* __restrict__ w_src, const float* __restrict__ b_src,
    const float* __restrict__ w_ref, const float* __restrict__ b_ref,
    const float* __restrict__ w_gate, const float* __restrict__ b_gate)
{
    __shared__ float Wsm[128][66];

    const int z = blockIdx.z;
    const int b = blockIdx.y;
    const int i = blockIdx.x * 256 + threadIdx.x;

    const float *X, *W, *bias;
    if (z == 0)      { X = src; W = w_src;                       bias = b_src; }
    else if (z == 1) { X = ref; W = w_ref;                       bias = b_ref; }
    else             { X = ref; W = w_gate + (z - 2) * 64 * CIN; bias = b_gate + (z - 2) * 64; }

    unsigned long long acc2[32];
    #pragma unroll
    for (int o = 0; o < 32; o++) acc2[o] = pk2(bias[2 * o], bias[2 * o + 1]);

    const float* Xp = X + (size_t)b * CIN * HW + i;

    for (int half = 0; half < 2; half++) {
        __syncthreads();
        for (int t = threadIdx.x; t < 64 * 128; t += 256) {
            int o = t >> 7, c = t & 127;
            Wsm[c][o] = W[o * CIN + half * 128 + c];
        }
        __syncthreads();
        #pragma unroll 4
        for (int c = 0; c < 128; c++) {
            float x = Xp[(half * 128 + c) * HW];
            unsigned long long xx = pk2(x, x);
            const unsigned long long* wr = (const unsigned long long*)&Wsm[c][0];
            #pragma unroll
            for (int o = 0; o < 32; o++) ffma2(acc2[o], wr[o], xx);
        }
    }

    if (z == 0 || z == 1) {
        __nv_bfloat16* outp = (z == 0 ? Qg : Kg) + ((size_t)b * HW + i) * DQK;
        #pragma unroll
        for (int o = 0; o < 32; o++) {
            float a, bb; upk2(acc2[o], a, bb);
            outp[2 * o]     = __float2bfloat16(a);
            outp[2 * o + 1] = __float2bfloat16(bb);
        }
    } else {
        const int ch0 = (z - 2) * 64;
        #pragma unroll
        for (int o = 0; o < 32; o++) {
            float a, bb; upk2(acc2[o], a, bb);
            Vtg[((size_t)(b * CIN + ch0 + 2 * o))     * HW + i] = __float2bfloat16(a);
            Vtg[((size_t)(b * CIN + ch0 + 2 * o + 1)) * HW + i] = __float2bfloat16(bb);
        }
    }
}

// ============================================================
// bf16 HMMA flash attention + epilogue.
// grid (HW/BQ=64, NB, 2): z selects 128 output channels.
// 128 threads; each warp: 16 query rows x 128 channels. oacc = 64 regs.
// ============================================================
__device__ __forceinline__ void issue_kv(uint32_t sb, int koff, int voff,
                                         int b, int z, int j0, int tid)
{
    // K tile: 64 rows x 128B (8 x 16B chunks), padded stride 144B
    const __nv_bfloat16* kp = Kg + ((size_t)b * HW + j0) * DQK;
    #pragma unroll
    for (int t = tid; t < 64 * 8; t += 128) {
        int r = t >> 3, c8 = t & 7;
        cp_async16(sb + koff + r * KROW + c8 * 16, kp + r * DQK + c8 * 8);
    }
    // V tile: this CTA's 128 channel rows x 128B
    #pragma unroll
    for (int t = tid; t < 128 * 8; t += 128) {
        int c = t >> 3, c8 = t & 7;
        cp_async16(sb + voff + c * VROW + c8 * 16,
                   Vtg + ((size_t)(b * CIN + z * CHPC + c)) * HW + j0 + c8 * 8);
    }
}

__global__ __launch_bounds__(128, 3) void attn_kernel(
    const float* __restrict__ srcf, const float* __restrict__ gammap,
    float* __restrict__ out)
{
    extern __shared__ char smem[];
    const uint32_t sb = smem_u32(smem);
    const int tid  = threadIdx.x;
    const int warp = tid >> 5;
    const int lane = tid & 31;
    const int b    = blockIdx.y;
    const int z    = blockIdx.z;
    const int q0   = blockIdx.x * BQ;
    const int qr   = (lane >> 2);        // row-in-tile 0..7
    const int m4   = (lane & 3);         // quad col

    // per-lane invariant offset for ldmatrix.x4 B-frag loads:
    // mat = lane>>3:  0 -> (tile, k lo), 1 -> (tile, k hi), 2/3 -> tile+1
    const uint32_t lmoff = (uint32_t)((((lane >> 4) & 1) * 8 + (lane & 7)) * KROW
                                      + ((lane >> 3) & 1) * 16);

    // prologue: Q (group 0), K0/V0 (group 1)
    {
        const __nv_bfloat16* qp = Qg + ((size_t)b * HW + q0) * DQK;
        #pragma unroll
        for (int t = tid; t < 64 * 8; t += 128) {
            int r = t >> 3, c8 = t & 7;
            cp_async16(sb + SM_Q + r * KROW + c8 * 16, qp + r * DQK + c8 * 8);
        }
        CP_COMMIT();
        issue_kv(sb, SM_K0, SM_V0, b, z, 0, tid);
        CP_COMMIT();
    }

    float oacc[64];
    #pragma unroll
    for (int i = 0; i < 64; i++) oacc[i] = 0.f;
    float den0 = 0.f, den1 = 0.f;
    uint32_t aq[4][4];

    const float SCL = 0.0625f * 1.44269504088896f;   // (1/16) * log2(e)

    #pragma unroll 1
    for (int j = 0; j < NITER; j++) {
        const int koff = (j & 1) ? SM_K1 : SM_K0;
        const int voff = (j & 1) ? SM_V1 : SM_V0;

        if (j + 1 < NITER) {
            issue_kv(sb, (j & 1) ? SM_K0 : SM_K1, (j & 1) ? SM_V0 : SM_V1,
                     b, z, (j + 1) * BK, tid);
            CP_COMMIT();
            asm volatile("cp.async.wait_group 1;" ::: "memory");
        } else {
            asm volatile("cp.async.wait_group 0;" ::: "memory");
        }
        __syncthreads();

        if (j == 0) {
            // Q A-frags, once: rows warp*16 + qr (+8), k-steps 0..3
            const uint32_t qbase = sb + SM_Q + (warp * 16 + qr) * KROW + m4 * 4;
            #pragma unroll
            for (int ks = 0; ks < 4; ks++) {
                aq[ks][0] = lds_b32(qbase + ks * 32);
                aq[ks][1] = lds_b32(qbase + 8 * KROW + ks * 32);
                aq[ks][2] = lds_b32(qbase + ks * 32 + 16);
                aq[ks][3] = lds_b32(qbase + 8 * KROW + ks * 32 + 16);
            }
        }

        // ---- S = Q K^T : 8 n-tiles via 4 ldmatrix.x4 per k-step ----
        float s[8][4];
        #pragma unroll
        for (int nt = 0; nt < 8; nt++)
            #pragma unroll
            for (int c = 0; c < 4; c++) s[nt][c] = 0.f;

        #pragma unroll
        for (int ks = 0; ks < 4; ks++) {
            const uint32_t kb = sb + koff + ks * 32 + lmoff;
            #pragma unroll
            for (int tp = 0; tp < 4; tp++) {
                uint32_t b0, b1, b2, b3;
                ldmx4(b0, b1, b2, b3, kb + tp * (16 * KROW));
                mma16816(s[2 * tp][0], s[2 * tp][1], s[2 * tp][2], s[2 * tp][3],
                         aq[ks][0], aq[ks][1], aq[ks][2], aq[ks][3], b0, b1);
                mma16816(s[2 * tp + 1][0], s[2 * tp + 1][1], s[2 * tp + 1][2], s[2 * tp + 1][3],
                         aq[ks][0], aq[ks][1], aq[ks][2], aq[ks][3], b2, b3);
            }
        }

        // ---- P = exp2(S * SCL), pack to bf16 A-frags, accumulate den ----
        uint32_t pa[4][4];
        #pragma unroll
        for (int ks = 0; ks < 4; ks++) {
            float e0a = exp2f(s[2 * ks][0] * SCL);
            float e1a = exp2f(s[2 * ks][1] * SCL);
            float e2a = exp2f(s[2 * ks][2] * SCL);
            float e3a = exp2f(s[2 * ks][3] * SCL);
            float e0b = exp2f(s[2 * ks + 1][0] * SCL);
            float e1b = exp2f(s[2 * ks + 1][1] * SCL);
            float e2b = exp2f(s[2 * ks + 1][2] * SCL);
            float e3b = exp2f(s[2 * ks + 1][3] * SCL);
            den0 += e0a + e1a + e0b + e1b;
            den1 += e2a + e3a + e2b + e3b;
            pa[ks][0] = cvt_bf16x2(e0a, e1a);
            pa[ks][1] = cvt_bf16x2(e2a, e3a);
            pa[ks][2] = cvt_bf16x2(e0b, e1b);
            pa[ks][3] = cvt_bf16x2(e2b, e3b);
        }

        // ---- O += P V^T : 16 channel n-tiles via 8 ldmatrix.x4 per k-step ----
        #pragma unroll
        for (int ks = 0; ks < 4; ks++) {
            const uint32_t vb = sb + voff + ks * 32 + lmoff;
            #pragma unroll
            for (int tp = 0; tp < 8; tp++) {
                uint32_t b0, b1, b2, b3;
                ldmx4(b0, b1, b2, b3, vb + tp * (16 * VROW));
                mma16816(oacc[8 * tp + 0], oacc[8 * tp + 1],
                         oacc[8 * tp + 2], oacc[8 * tp + 3],
                         pa[ks][0], pa[ks][1], pa[ks][2], pa[ks][3], b0, b1);
                mma16816(oacc[8 * tp + 4], oacc[8 * tp + 5],
                         oacc[8 * tp + 6], oacc[8 * tp + 7],
                         pa[ks][0], pa[ks][1], pa[ks][2], pa[ks][3], b2, b3);
            }
        }
        __syncthreads();   // done with this buffer before it is refilled
    }

    // ---- den reduction across quad (cols) ----
    den0 += __shfl_xor_sync(0xffffffffu, den0, 1);
    den0 += __shfl_xor_sync(0xffffffffu, den0, 2);
    den1 += __shfl_xor_sync(0xffffffffu, den1, 1);
    den1 += __shfl_xor_sync(0xffffffffu, den1, 2);
    const float gamma = __ldg(gammap);
    const float s0 = gamma / den0;
    const float s1 = gamma / den1;

    // ---- epilogue: stage 64-channel chunks in SMEM, coalesced out ----
    float* stg = (float*)(smem + SM_STG);     // [64 ch][68] floats
    const float* sp = srcf + (size_t)b * CIN * HW;
    float*       op = out  + (size_t)b * CIN * HW;
    const int qloc = warp * 16 + qr;

    #pragma unroll 1
    for (int cc = 0; cc < 2; cc++) {
        __syncthreads();
        #pragma unroll
        for (int nt8 = 0; nt8 < 8; nt8++) {
            int nt = cc * 8 + nt8;
            int ch = nt8 * 8 + 2 * m4;
            stg[ch * 68 + qloc]           = oacc[nt * 4 + 0] * s0;
            stg[(ch + 1) * 68 + qloc]     = oacc[nt * 4 + 1] * s0;
            stg[ch * 68 + qloc + 8]       = oacc[nt * 4 + 2] * s1;
            stg[(ch + 1) * 68 + qloc + 8] = oacc[nt * 4 + 3] * s1;
        }
        __syncthreads();
        #pragma unroll
        for (int idx = tid; idx < 64 * 64; idx += 128) {
            int ch = idx >> 6, q = idx & 63;
            size_t g = (size_t)(z * CHPC + cc * 64 + ch) * HW + q0 + q;
            op[g] = stg[ch * 68 + q] + sp[g];
        }
    }
}

// ============================================================
extern "C" void kernel_launch(void* const* d_in, const int* in_sizes, int n_in,
                              void* d_out, int out_size)
{
    const float* src    = (const float*)d_in[0];
    const float* ref    = (const float*)d_in[1];
    const float* w_src  = (const float*)d_in[2];
    const float* b_src  = (const float*)d_in[3];
    const float* w_ref  = (const float*)d_in[4];
    const float* b_ref  = (const float*)d_in[5];
    const float* w_gate = (const float*)d_in[6];
    const float* b_gate = (const float*)d_in[7];
    const float* gamma  = (const float*)d_in[8];
    float* out = (float*)d_out;

    cudaFuncSetAttribute(attn_kernel, cudaFuncAttributeMaxDynamicSharedMemorySize,
                         SM_TOTAL);

    proj_kernel<<<dim3(HW / 256, NB, 6), 256>>>(src, ref, w_src, b_src,
                                                w_ref, b_ref, w_gate, b_gate);
    attn_kernel<<<dim3(HW / BQ, NB, 2), 128, SM_TOTAL>>>(src, gamma, out);
}

// round 7
// speedup vs baseline: 4.2775x; 1.0174x over previous
#include <cuda_runtime.h>
#include <cuda_bf16.h>
#include <cstdint>

#define HW   4096
#define NB   4
#define CIN  256
#define DQK  64
#define BQ   64           // queries per CTA
#define BK   64           // keys per iteration
#define NITER (HW / BK)   // 64
#define CHPC 128          // channels per CTA (z-split)

// (1/16) * log2(e), folded into Q at projection time
#define QSCL (0.0625f * 1.44269504088896f)
#define ONESB2 0x3F803F80u   /* bf16x2 {1.0, 1.0} */

// ---------------- scratch (bf16) ----------------
__device__ __nv_bfloat16 Qg[NB * HW * DQK];        // [b][i][k]   2 MB (pre-scaled)
__device__ __nv_bfloat16 Kg[NB * HW * DQK];        // [b][j][k]   2 MB
__device__ __nv_bfloat16 Vtg[NB * CIN * HW];       // [b][c][j]   8 MB (channel-major)

// ---------------- helpers ----------------
__device__ __forceinline__ uint32_t smem_u32(const void* p) {
    uint32_t a;
    asm("{ .reg .u64 t; cvta.to.shared.u64 t, %1; cvt.u32.u64 %0, t; }" : "=r"(a) : "l"(p));
    return a;
}
__device__ __forceinline__ void cp_async16(uint32_t dst, const void* src) {
    asm volatile("cp.async.cg.shared.global [%0], [%1], 16;" :: "r"(dst), "l"(src));
}
#define CP_COMMIT() asm volatile("cp.async.commit_group;" ::: "memory")

__device__ __forceinline__ uint32_t lds_b32(uint32_t a) {
    uint32_t v;
    asm volatile("ld.shared.b32 %0, [%1];" : "=r"(v) : "r"(a));
    return v;
}
__device__ __forceinline__ void ldmx4(uint32_t* r, uint32_t a) {
    asm volatile("ldmatrix.sync.aligned.m8n8.x4.shared.b16 {%0,%1,%2,%3}, [%4];"
                 : "=r"(r[0]), "=r"(r[1]), "=r"(r[2]), "=r"(r[3]) : "r"(a));
}
__device__ __forceinline__ uint32_t cvt_bf16x2(float lo, float hi) {
    uint32_t r;
    asm("cvt.rn.bf16x2.f32 %0, %1, %2;" : "=r"(r) : "f"(hi), "f"(lo));
    return r;
}
__device__ __forceinline__ uint32_t ex2_b2(uint32_t x) {
    uint32_t r;
    asm("ex2.approx.ftz.bf16x2 %0, %1;" : "=r"(r) : "r"(x));
    return r;
}
// D += A(16x16,row) * B(16x8,col)  bf16 -> f32
__device__ __forceinline__ void mma16816(float& c0, float& c1, float& c2, float& c3,
                                         uint32_t a0, uint32_t a1, uint32_t a2, uint32_t a3,
                                         uint32_t b0, uint32_t b1) {
    asm volatile(
        "mma.sync.aligned.m16n8k16.row.col.f32.bf16.bf16.f32 "
        "{%0,%1,%2,%3}, {%4,%5,%6,%7}, {%8,%9}, {%0,%1,%2,%3};"
        : "+f"(c0), "+f"(c1), "+f"(c2), "+f"(c3)
        : "r"(a0), "r"(a1), "r"(a2), "r"(a3), "r"(b0), "r"(b1));
}

// packed f32x2 (projection kernel)
__device__ __forceinline__ unsigned long long pk2(float a, float b) {
    unsigned long long r;
    asm("mov.b64 %0, {%1, %2};" : "=l"(r) : "r"(__float_as_int(a)), "r"(__float_as_int(b)));
    return r;
}
__device__ __forceinline__ void upk2(unsigned long long v, float& a, float& b) {
    int x, y;
    asm("mov.b64 {%0, %1}, %2;" : "=r"(x), "=r"(y) : "l"(v));
    a = __int_as_float(x); b = __int_as_float(y);
}
__device__ __forceinline__ void ffma2(unsigned long long& d, unsigned long long a, unsigned long long b) {
    asm("fma.rn.f32x2 %0, %1, %2, %0;" : "+l"(d) : "l"(a), "l"(b));
}

// ---------------- SMEM layout (bytes) ----------------
// padded rows: 72 halves = 144 B per logical 64-half row (9 x 16B: ldmatrix conflict-free)
#define KROW    144
#define VROW    144
#define SM_Q    0                  // 64  x 144 =  9216
#define SM_K0   9216               // 64  x 144 =  9216
#define SM_K1   18432
#define SM_V0   27648              // 128 x 144 = 18432
#define SM_V1   46080
#define SM_TOTAL 64512
#define SM_STG  9216               // epilogue staging (reuses K bufs): 64*68*4 = 17408

// ============================================================
// Projection kernel (fp32 math, bf16 outputs; V written channel-major)
// grid (16, NB, 6): z=0->Q (pre-scaled), z=1->K, z=2..5 -> V channels
// ============================================================
__global__ __launch_bounds__(256) void proj_kernel(
    const float* __restrict__ src, const float* __restrict__ ref,
    const float* __restrict__ w_src, const float* __restrict__ b_src,
    const float* __restrict__ w_ref, const float* __restrict__ b_ref,
    const float* __restrict__ w_gate, const float* __restrict__ b_gate)
{
    __shared__ float Wsm[128][66];

    const int z = blockIdx.z;
    const int b = blockIdx.y;
    const int i = blockIdx.x * 256 + threadIdx.x;

    const float *X, *W, *bias;
    if (z == 0)      { X = src; W = w_src;                       bias = b_src; }
    else if (z == 1) { X = ref; W = w_ref;                       bias = b_ref; }
    else             { X = ref; W = w_gate + (z - 2) * 64 * CIN; bias = b_gate + (z - 2) * 64; }

    unsigned long long acc2[32];
    #pragma unroll
    for (int o = 0; o < 32; o++) acc2[o] = pk2(bias[2 * o], bias[2 * o + 1]);

    const float* Xp = X + (size_t)b * CIN * HW + i;

    for (int half = 0; half < 2; half++) {
        __syncthreads();
        for (int t = threadIdx.x; t < 64 * 128; t += 256) {
            int o = t >> 7, c = t & 127;
            Wsm[c][o] = W[o * CIN + half * 128 + c];
        }
        __syncthreads();
        #pragma unroll 4
        for (int c = 0; c < 128; c++) {
            float x = Xp[(half * 128 + c) * HW];
            unsigned long long xx = pk2(x, x);
            const unsigned long long* wr = (const unsigned long long*)&Wsm[c][0];
            #pragma unroll
            for (int o = 0; o < 32; o++) ffma2(acc2[o], wr[o], xx);
        }
    }

    if (z == 0) {
        __nv_bfloat16* outp = Qg + ((size_t)b * HW + i) * DQK;
        #pragma unroll
        for (int o = 0; o < 32; o++) {
            float a, bb; upk2(acc2[o], a, bb);
            outp[2 * o]     = __float2bfloat16(a * QSCL);
            outp[2 * o + 1] = __float2bfloat16(bb * QSCL);
        }
    } else if (z == 1) {
        __nv_bfloat16* outp = Kg + ((size_t)b * HW + i) * DQK;
        #pragma unroll
        for (int o = 0; o < 32; o++) {
            float a, bb; upk2(acc2[o], a, bb);
            outp[2 * o]     = __float2bfloat16(a);
            outp[2 * o + 1] = __float2bfloat16(bb);
        }
    } else {
        const int ch0 = (z - 2) * 64;
        #pragma unroll
        for (int o = 0; o < 32; o++) {
            float a, bb; upk2(acc2[o], a, bb);
            Vtg[((size_t)(b * CIN + ch0 + 2 * o))     * HW + i] = __float2bfloat16(a);
            Vtg[((size_t)(b * CIN + ch0 + 2 * o + 1)) * HW + i] = __float2bfloat16(bb);
        }
    }
}

// ============================================================
// bf16 HMMA flash attention + epilogue.
// grid (HW/BQ=64, NB, 2): z selects 128 output channels.
// 128 threads; each warp: 16 query rows x 128 channels.
// ============================================================
__device__ __forceinline__ void issue_kv(uint32_t sb, int koff, int voff,
                                         int b, int z, int j0, int tid)
{
    const __nv_bfloat16* kp = Kg + ((size_t)b * HW + j0) * DQK;
    #pragma unroll
    for (int t = tid; t < 64 * 8; t += 128) {
        int r = t >> 3, c8 = t & 7;
        cp_async16(sb + koff + r * KROW + c8 * 16, kp + r * DQK + c8 * 8);
    }
    #pragma unroll
    for (int t = tid; t < 128 * 8; t += 128) {
        int c = t >> 3, c8 = t & 7;
        cp_async16(sb + voff + c * VROW + c8 * 16,
                   Vtg + ((size_t)(b * CIN + z * CHPC + c)) * HW + j0 + c8 * 8);
    }
}

__global__ __launch_bounds__(128, 3) void attn_kernel(
    const float* __restrict__ srcf, const float* __restrict__ gammap,
    float* __restrict__ out)
{
    extern __shared__ char smem[];
    const uint32_t sb = smem_u32(smem);
    const int tid  = threadIdx.x;
    const int warp = tid >> 5;
    const int lane = tid & 31;
    const int b    = blockIdx.y;
    const int z    = blockIdx.z;
    const int q0   = blockIdx.x * BQ;
    const int qr   = (lane >> 2);        // row-in-tile 0..7
    const int m4   = (lane & 3);         // quad col

    // per-lane invariant offset for ldmatrix.x4 B-frag loads
    const uint32_t lmoff = (uint32_t)((((lane >> 4) & 1) * 8 + (lane & 7)) * KROW
                                      + ((lane >> 3) & 1) * 16);

    // prologue: Q (group 0), K0/V0 (group 1)
    {
        const __nv_bfloat16* qp = Qg + ((size_t)b * HW + q0) * DQK;
        #pragma unroll
        for (int t = tid; t < 64 * 8; t += 128) {
            int r = t >> 3, c8 = t & 7;
            cp_async16(sb + SM_Q + r * KROW + c8 * 16, qp + r * DQK + c8 * 8);
        }
        CP_COMMIT();
        issue_kv(sb, SM_K0, SM_V0, b, z, 0, tid);
        CP_COMMIT();
    }

    // wait for Q only (K0/V0 still in flight), then load Q A-frags once
    uint32_t aq[4][4];
    {
        asm volatile("cp.async.wait_group 1;" ::: "memory");
        __syncthreads();
        const uint32_t qbase = sb + SM_Q + (warp * 16 + qr) * KROW + m4 * 4;
        #pragma unroll
        for (int ks = 0; ks < 4; ks++) {
            aq[ks][0] = lds_b32(qbase + ks * 32);
            aq[ks][1] = lds_b32(qbase + 8 * KROW + ks * 32);
            aq[ks][2] = lds_b32(qbase + ks * 32 + 16);
            aq[ks][3] = lds_b32(qbase + 8 * KROW + ks * 32 + 16);
        }
    }

    float oacc[64];
    #pragma unroll
    for (int i = 0; i < 64; i++) oacc[i] = 0.f;
    float dden[4];
    #pragma unroll
    for (int i = 0; i < 4; i++) dden[i] = 0.f;

    #pragma unroll 1
    for (int j = 0; j < NITER; j++) {
        const int koff = (j & 1) ? SM_K1 : SM_K0;
        const int voff = (j & 1) ? SM_V1 : SM_V0;

        if (j + 1 < NITER) {
            issue_kv(sb, (j & 1) ? SM_K0 : SM_K1, (j & 1) ? SM_V0 : SM_V1,
                     b, z, (j + 1) * BK, tid);
            CP_COMMIT();
            asm volatile("cp.async.wait_group 1;" ::: "memory");
        } else {
            asm volatile("cp.async.wait_group 0;" ::: "memory");
        }
        __syncthreads();

        // ---- fused S + softmax, one 16-key slab (tp) at a time ----
        // addr(ks,tp) = kbase + ks*32 + tp*16*KROW ; depth-1 frag pipeline
        uint32_t pa[4][4];
        {
            const uint32_t kbase = sb + koff + lmoff;
            uint32_t kf[2][4];
            ldmx4(kf[0], kbase);
            #pragma unroll
            for (int tp = 0; tp < 4; tp++) {
                float s0[4] = {0.f, 0.f, 0.f, 0.f};
                float s1[4] = {0.f, 0.f, 0.f, 0.f};
                #pragma unroll
                for (int ks = 0; ks < 4; ks++) {
                    const int cur = ks & 1;
                    if (!(tp == 3 && ks == 3)) {
                        const int nks = (ks + 1) & 3;
                        const int ntp = tp + (ks == 3 ? 1 : 0);
                        ldmx4(kf[cur ^ 1], kbase + nks * 32 + ntp * (16 * KROW));
                    }
                    mma16816(s0[0], s0[1], s0[2], s0[3],
                             aq[ks][0], aq[ks][1], aq[ks][2], aq[ks][3],
                             kf[cur][0], kf[cur][1]);
                    mma16816(s1[0], s1[1], s1[2], s1[3],
                             aq[ks][0], aq[ks][1], aq[ks][2], aq[ks][3],
                             kf[cur][2], kf[cur][3]);
                }
                // P = 2^S (S pre-scaled via Q); bf16-domain exp
                pa[tp][0] = ex2_b2(cvt_bf16x2(s0[0], s0[1]));
                pa[tp][1] = ex2_b2(cvt_bf16x2(s0[2], s0[3]));
                pa[tp][2] = ex2_b2(cvt_bf16x2(s1[0], s1[1]));
                pa[tp][3] = ex2_b2(cvt_bf16x2(s1[2], s1[3]));
                // den += P . ones  (row sums, replicated across columns)
                mma16816(dden[0], dden[1], dden[2], dden[3],
                         pa[tp][0], pa[tp][1], pa[tp][2], pa[tp][3],
                         ONESB2, ONESB2);
            }
        }

        // ---- O += P V^T : 16 channel n-tiles, depth-2 frag pipeline ----
        {
            const uint32_t vbase = sb + voff + lmoff;
            uint32_t vf[3][4];
            ldmx4(vf[0], vbase);                    // (ks=0, tp=0)
            ldmx4(vf[1], vbase + 16 * VROW);        // (ks=0, tp=1)
            #pragma unroll
            for (int ks = 0; ks < 4; ks++) {
                #pragma unroll
                for (int tp = 0; tp < 8; tp++) {
                    const int n = ks * 8 + tp;
                    const int cur = n % 3;
                    if (n + 2 < 32) {
                        const int nn = n + 2;
                        ldmx4(vf[(n + 2) % 3],
                              vbase + (nn >> 3) * 32 + (nn & 7) * (16 * VROW));
                    }
                    mma16816(oacc[8 * tp + 0], oacc[8 * tp + 1],
                             oacc[8 * tp + 2], oacc[8 * tp + 3],
                             pa[ks][0], pa[ks][1], pa[ks][2], pa[ks][3],
                             vf[cur][0], vf[cur][1]);
                    mma16816(oacc[8 * tp + 4], oacc[8 * tp + 5],
                             oacc[8 * tp + 6], oacc[8 * tp + 7],
                             pa[ks][0], pa[ks][1], pa[ks][2], pa[ks][3],
                             vf[cur][2], vf[cur][3]);
                }
            }
        }
        __syncthreads();   // done with this buffer before it is refilled
    }

    // den: dden[0] = row qr, dden[2] = row qr+8 (replicated across quad cols)
    const float gamma = __ldg(gammap);
    const float s0 = gamma / dden[0];
    const float s1 = gamma / dden[2];

    // ---- epilogue: stage 64-channel chunks in SMEM, coalesced out ----
    float* stg = (float*)(smem + SM_STG);     // [64 ch][68] floats
    const float* sp = srcf + (size_t)b * CIN * HW;
    float*       op = out  + (size_t)b * CIN * HW;
    const int qloc = warp * 16 + qr;

    #pragma unroll 1
    for (int cc = 0; cc < 2; cc++) {
        __syncthreads();
        #pragma unroll
        for (int nt8 = 0; nt8 < 8; nt8++) {
            int nt = cc * 8 + nt8;
            int ch = nt8 * 8 + 2 * m4;
            stg[ch * 68 + qloc]           = oacc[nt * 4 + 0] * s0;
            stg[(ch + 1) * 68 + qloc]     = oacc[nt * 4 + 1] * s0;
            stg[ch * 68 + qloc + 8]       = oacc[nt * 4 + 2] * s1;
            stg[(ch + 1) * 68 + qloc + 8] = oacc[nt * 4 + 3] * s1;
        }
        __syncthreads();
        #pragma unroll
        for (int idx = tid; idx < 64 * 64; idx += 128) {
            int ch = idx >> 6, q = idx & 63;
            size_t g = (size_t)(z * CHPC + cc * 64 + ch) * HW + q0 + q;
            op[g] = stg[ch * 68 + q] + sp[g];
        }
    }
}

// ============================================================
extern "C" void kernel_launch(void* const* d_in, const int* in_sizes, int n_in,
                              void* d_out, int out_size)
{
    const float* src    = (const float*)d_in[0];
    const float* ref    = (const float*)d_in[1];
    const float* w_src  = (const float*)d_in[2];
    const float* b_src  = (const float*)d_in[3];
    const float* w_ref  = (const float*)d_in[4];
    const float* b_ref  = (const float*)d_in[5];
    const float* w_gate = (const float*)d_in[6];
    const float* b_gate = (const float*)d_in[7];
    const float* gamma  = (const float*)d_in[8];
    float* out = (float*)d_out;

    cudaFuncSetAttribute(attn_kernel, cudaFuncAttributeMaxDynamicSharedMemorySize,
                         SM_TOTAL);

    proj_kernel<<<dim3(HW / 256, NB, 6), 256>>>(src, ref, w_src, b_src,
                                                w_ref, b_ref, w_gate, b_gate);
    attn_kernel<<<dim3(HW / BQ, NB, 2), 128, SM_TOTAL>>>(src, gamma, out);
}

// round 8
// speedup vs baseline: 5.2428x; 1.2257x over previous
#include <cuda_runtime.h>
#include <cuda_bf16.h>
#include <cstdint>

#define HW   4096
#define NB   4
#define CIN  256
#define DQK  64
#define BQ   128          // queries per CTA (4 warps x 32 rows)
#define BK   64           // keys per iteration
#define NITER (HW / BK)   // 64
#define CHPC 64           // channels per CTA (z-split x4)

// (1/16) * log2(e), folded into Q at projection time
#define QSCL (0.0625f * 1.44269504088896f)
#define ONESB2 0x3F803F80u   /* bf16x2 {1.0, 1.0} */

// ---------------- scratch (bf16) ----------------
__device__ __nv_bfloat16 Qg[NB * HW * DQK];        // [b][i][k]   2 MB (pre-scaled)
__device__ __nv_bfloat16 Kg[NB * HW * DQK];        // [b][j][k]   2 MB
__device__ __nv_bfloat16 Vtg[NB * CIN * HW];       // [b][c][j]   8 MB (channel-major)

// ---------------- helpers ----------------
__device__ __forceinline__ uint32_t smem_u32(const void* p) {
    uint32_t a;
    asm("{ .reg .u64 t; cvta.to.shared.u64 t, %1; cvt.u32.u64 %0, t; }" : "=r"(a) : "l"(p));
    return a;
}
__device__ __forceinline__ void cp_async16(uint32_t dst, const void* src) {
    asm volatile("cp.async.cg.shared.global [%0], [%1], 16;" :: "r"(dst), "l"(src));
}
#define CP_COMMIT() asm volatile("cp.async.commit_group;" ::: "memory")

__device__ __forceinline__ uint32_t lds_b32(uint32_t a) {
    uint32_t v;
    asm volatile("ld.shared.b32 %0, [%1];" : "=r"(v) : "r"(a));
    return v;
}
__device__ __forceinline__ void ldmx4(uint32_t* r, uint32_t a) {
    asm volatile("ldmatrix.sync.aligned.m8n8.x4.shared.b16 {%0,%1,%2,%3}, [%4];"
                 : "=r"(r[0]), "=r"(r[1]), "=r"(r[2]), "=r"(r[3]) : "r"(a));
}
__device__ __forceinline__ uint32_t cvt_bf16x2(float lo, float hi) {
    uint32_t r;
    asm("cvt.rn.bf16x2.f32 %0, %1, %2;" : "=r"(r) : "f"(hi), "f"(lo));
    return r;
}
__device__ __forceinline__ uint32_t ex2_b2(uint32_t x) {
    uint32_t r;
    asm("ex2.approx.ftz.bf16x2 %0, %1;" : "=r"(r) : "r"(x));
    return r;
}
// D += A(16x16,row) * B(16x8,col)  bf16 -> f32
__device__ __forceinline__ void mma16816(float* c,
                                         uint32_t a0, uint32_t a1, uint32_t a2, uint32_t a3,
                                         uint32_t b0, uint32_t b1) {
    asm volatile(
        "mma.sync.aligned.m16n8k16.row.col.f32.bf16.bf16.f32 "
        "{%0,%1,%2,%3}, {%4,%5,%6,%7}, {%8,%9}, {%0,%1,%2,%3};"
        : "+f"(c[0]), "+f"(c[1]), "+f"(c[2]), "+f"(c[3])
        : "r"(a0), "r"(a1), "r"(a2), "r"(a3), "r"(b0), "r"(b1));
}

// packed f32x2 (projection kernel)
__device__ __forceinline__ unsigned long long pk2(float a, float b) {
    unsigned long long r;
    asm("mov.b64 %0, {%1, %2};" : "=l"(r) : "r"(__float_as_int(a)), "r"(__float_as_int(b)));
    return r;
}
__device__ __forceinline__ void upk2(unsigned long long v, float& a, float& b) {
    int x, y;
    asm("mov.b64 {%0, %1}, %2;" : "=r"(x), "=r"(y) : "l"(v));
    a = __int_as_float(x); b = __int_as_float(y);
}
__device__ __forceinline__ void ffma2(unsigned long long& d, unsigned long long a, unsigned long long b) {
    asm("fma.rn.f32x2 %0, %1, %2, %0;" : "+l"(d) : "l"(a), "l"(b));
}

// ---------------- SMEM layout (bytes) ----------------
// padded rows: 72 halves = 144 B per row (9 x 16B: ldmatrix conflict-free)
#define KROW    144
#define VROW    144
#define SM_Q    0                  // 128 x 144 = 18432
#define SM_K0   18432              // 64  x 144 =  9216
#define SM_K1   27648
#define SM_V0   36864              // 64  x 144 =  9216
#define SM_V1   46080
#define SM_TOTAL 55296
#define SM_STG  18432              // epilogue staging (reuses K/V): 64*132*4 = 33792

// ============================================================
// Projection kernel (fp32 math, bf16 outputs; V written channel-major)
// grid (16, NB, 6): z=0->Q (pre-scaled), z=1->K, z=2..5 -> V channels
// ============================================================
__global__ __launch_bounds__(256) void proj_kernel(
    const float* __restrict__ src, const float* __restrict__ ref,
    const float* __restrict__ w_src, const float* __restrict__ b_src,
    const float* __restrict__ w_ref, const float* __restrict__ b_ref,
    const float* __restrict__ w_gate, const float* __restrict__ b_gate)
{
    __shared__ float Wsm[128][66];

    const int z = blockIdx.z;
    const int b = blockIdx.y;
    const int i = blockIdx.x * 256 + threadIdx.x;

    const float *X, *W, *bias;
    if (z == 0)      { X = src; W = w_src;                       bias = b_src; }
    else if (z == 1) { X = ref; W = w_ref;                       bias = b_ref; }
    else             { X = ref; W = w_gate + (z - 2) * 64 * CIN; bias = b_gate + (z - 2) * 64; }

    unsigned long long acc2[32];
    #pragma unroll
    for (int o = 0; o < 32; o++) acc2[o] = pk2(bias[2 * o], bias[2 * o + 1]);

    const float* Xp = X + (size_t)b * CIN * HW + i;

    for (int half = 0; half < 2; half++) {
        __syncthreads();
        for (int t = threadIdx.x; t < 64 * 128; t += 256) {
            int o = t >> 7, c = t & 127;
            Wsm[c][o] = W[o * CIN + half * 128 + c];
        }
        __syncthreads();
        #pragma unroll 4
        for (int c = 0; c < 128; c++) {
            float x = Xp[(half * 128 + c) * HW];
            unsigned long long xx = pk2(x, x);
            const unsigned long long* wr = (const unsigned long long*)&Wsm[c][0];
            #pragma unroll
            for (int o = 0; o < 32; o++) ffma2(acc2[o], wr[o], xx);
        }
    }

    if (z == 0) {
        __nv_bfloat16* outp = Qg + ((size_t)b * HW + i) * DQK;
        #pragma unroll
        for (int o = 0; o < 32; o++) {
            float a, bb; upk2(acc2[o], a, bb);
            outp[2 * o]     = __float2bfloat16(a * QSCL);
            outp[2 * o + 1] = __float2bfloat16(bb * QSCL);
        }
    } else if (z == 1) {
        __nv_bfloat16* outp = Kg + ((size_t)b * HW + i) * DQK;
        #pragma unroll
        for (int o = 0; o < 32; o++) {
            float a, bb; upk2(acc2[o], a, bb);
            outp[2 * o]     = __float2bfloat16(a);
            outp[2 * o + 1] = __float2bfloat16(bb);
        }
    } else {
        const int ch0 = (z - 2) * 64;
        #pragma unroll
        for (int o = 0; o < 32; o++) {
            float a, bb; upk2(acc2[o], a, bb);
            Vtg[((size_t)(b * CIN + ch0 + 2 * o))     * HW + i] = __float2bfloat16(a);
            Vtg[((size_t)(b * CIN + ch0 + 2 * o + 1)) * HW + i] = __float2bfloat16(bb);
        }
    }
}

// ============================================================
// bf16 HMMA flash attention + epilogue.
// grid (HW/BQ=32, NB, 4): z selects 64 output channels.
// 128 threads; warp w: rows w*32..w*32+31 (2 m-tiles) x 64 channels.
// ============================================================
__device__ __forceinline__ void issue_kv(uint32_t sb, int koff, int voff,
                                         int b, int z, int j0, int tid)
{
    const __nv_bfloat16* kp = Kg + ((size_t)b * HW + j0) * DQK;
    #pragma unroll
    for (int t = tid; t < 64 * 8; t += 128) {
        int r = t >> 3, c8 = t & 7;
        cp_async16(sb + koff + r * KROW + c8 * 16, kp + r * DQK + c8 * 8);
    }
    #pragma unroll
    for (int t = tid; t < 64 * 8; t += 128) {
        int c = t >> 3, c8 = t & 7;
        cp_async16(sb + voff + c * VROW + c8 * 16,
                   Vtg + ((size_t)(b * CIN + z * CHPC + c)) * HW + j0 + c8 * 8);
    }
}

__global__ __launch_bounds__(128, 3) void attn_kernel(
    const float* __restrict__ srcf, const float* __restrict__ gammap,
    float* __restrict__ out)
{
    extern __shared__ char smem[];
    const uint32_t sb = smem_u32(smem);
    const int tid  = threadIdx.x;
    const int warp = tid >> 5;
    const int lane = tid & 31;
    const int b    = blockIdx.y;
    const int z    = blockIdx.z;
    const int q0   = blockIdx.x * BQ;
    const int qr   = (lane >> 2);        // row-in-tile 0..7
    const int m4   = (lane & 3);         // quad col

    // per-lane invariant offset for ldmatrix.x4 B-frag loads
    const uint32_t lmoff = (uint32_t)((((lane >> 4) & 1) * 8 + (lane & 7)) * KROW
                                      + ((lane >> 3) & 1) * 16);

    // prologue: Q (group 0), K0/V0 (group 1)
    {
        const __nv_bfloat16* qp = Qg + ((size_t)b * HW + q0) * DQK;
        #pragma unroll
        for (int t = tid; t < 128 * 8; t += 128) {
            int r = t >> 3, c8 = t & 7;
            cp_async16(sb + SM_Q + r * KROW + c8 * 16, qp + r * DQK + c8 * 8);
        }
        CP_COMMIT();
        issue_kv(sb, SM_K0, SM_V0, b, z, 0, tid);
        CP_COMMIT();
    }

    // wait for Q only, load Q A-frags (2 m-tiles) once
    uint32_t aq[2][4][4];
    {
        asm volatile("cp.async.wait_group 1;" ::: "memory");
        __syncthreads();
        #pragma unroll
        for (int mt = 0; mt < 2; mt++) {
            const uint32_t qbase = sb + SM_Q + (warp * 32 + mt * 16 + qr) * KROW + m4 * 4;
            #pragma unroll
            for (int ks = 0; ks < 4; ks++) {
                aq[mt][ks][0] = lds_b32(qbase + ks * 32);
                aq[mt][ks][1] = lds_b32(qbase + 8 * KROW + ks * 32);
                aq[mt][ks][2] = lds_b32(qbase + ks * 32 + 16);
                aq[mt][ks][3] = lds_b32(qbase + 8 * KROW + ks * 32 + 16);
            }
        }
    }

    float oacc[2][8][4];
    #pragma unroll
    for (int mt = 0; mt < 2; mt++)
        #pragma unroll
        for (int nt = 0; nt < 8; nt++)
            #pragma unroll
            for (int c = 0; c < 4; c++) oacc[mt][nt][c] = 0.f;
    float dden[2][4];
    #pragma unroll
    for (int mt = 0; mt < 2; mt++)
        #pragma unroll
        for (int c = 0; c < 4; c++) dden[mt][c] = 0.f;

    #pragma unroll 1
    for (int j = 0; j < NITER; j++) {
        const int koff = (j & 1) ? SM_K1 : SM_K0;
        const int voff = (j & 1) ? SM_V1 : SM_V0;

        if (j + 1 < NITER) {
            issue_kv(sb, (j & 1) ? SM_K0 : SM_K1, (j & 1) ? SM_V0 : SM_V1,
                     b, z, (j + 1) * BK, tid);
            CP_COMMIT();
            asm volatile("cp.async.wait_group 1;" ::: "memory");
        } else {
            asm volatile("cp.async.wait_group 0;" ::: "memory");
        }
        __syncthreads();

        const uint32_t kbase = sb + koff + lmoff;
        const uint32_t vbase = sb + voff + lmoff;

        // ---- fused: per 16-key slab: S -> exp -> PV ----
        #pragma unroll
        for (int tp = 0; tp < 4; tp++) {
            // K frags for this slab (2 n-tiles x 4 k-steps)
            uint32_t kf[4][4];
            #pragma unroll
            for (int ks = 0; ks < 4; ks++)
                ldmx4(kf[ks], kbase + tp * (16 * KROW) + ks * 32);

            // S = Q K^T for 2 m-tiles x 16 keys
            float s[2][2][4];
            #pragma unroll
            for (int mt = 0; mt < 2; mt++)
                #pragma unroll
                for (int nh = 0; nh < 2; nh++)
                    #pragma unroll
                    for (int c = 0; c < 4; c++) s[mt][nh][c] = 0.f;
            #pragma unroll
            for (int ks = 0; ks < 4; ks++)
                #pragma unroll
                for (int mt = 0; mt < 2; mt++) {
                    mma16816(s[mt][0], aq[mt][ks][0], aq[mt][ks][1],
                             aq[mt][ks][2], aq[mt][ks][3], kf[ks][0], kf[ks][1]);
                    mma16816(s[mt][1], aq[mt][ks][0], aq[mt][ks][1],
                             aq[mt][ks][2], aq[mt][ks][3], kf[ks][2], kf[ks][3]);
                }

            // P = 2^S (pre-scaled), packed to PV A-frags; den += P . ones
            uint32_t pa[2][4];
            #pragma unroll
            for (int mt = 0; mt < 2; mt++) {
                pa[mt][0] = ex2_b2(cvt_bf16x2(s[mt][0][0], s[mt][0][1]));
                pa[mt][1] = ex2_b2(cvt_bf16x2(s[mt][0][2], s[mt][0][3]));
                pa[mt][2] = ex2_b2(cvt_bf16x2(s[mt][1][0], s[mt][1][1]));
                pa[mt][3] = ex2_b2(cvt_bf16x2(s[mt][1][2], s[mt][1][3]));
                mma16816(dden[mt], pa[mt][0], pa[mt][1], pa[mt][2], pa[mt][3],
                         ONESB2, ONESB2);
            }

            // V frags for this k-slab (4 channel-tile-pairs), PV MMAs
            #pragma unroll
            for (int ntp = 0; ntp < 4; ntp++) {
                uint32_t vf[4];
                ldmx4(vf, vbase + tp * 32 + ntp * (16 * VROW));
                #pragma unroll
                for (int mt = 0; mt < 2; mt++) {
                    mma16816(oacc[mt][2 * ntp],     pa[mt][0], pa[mt][1],
                             pa[mt][2], pa[mt][3], vf[0], vf[1]);
                    mma16816(oacc[mt][2 * ntp + 1], pa[mt][0], pa[mt][1],
                             pa[mt][2], pa[mt][3], vf[2], vf[3]);
                }
            }
        }
        __syncthreads();   // done with this buffer before it is refilled
    }

    // row sums are replicated across quad cols: dden[mt][0] = row qr, [2] = row qr+8
    const float gamma = __ldg(gammap);
    float scl[2][2];
    #pragma unroll
    for (int mt = 0; mt < 2; mt++) {
        scl[mt][0] = gamma / dden[mt][0];
        scl[mt][1] = gamma / dden[mt][2];
    }

    // ---- epilogue: stage [64 ch][132] floats in SMEM, coalesced out ----
    float* stg = (float*)(smem + SM_STG);
    const float* sp = srcf + (size_t)b * CIN * HW;
    float*       op = out  + (size_t)b * CIN * HW;

    #pragma unroll
    for (int mt = 0; mt < 2; mt++) {
        const int q = warp * 32 + mt * 16 + qr;
        #pragma unroll
        for (int nt = 0; nt < 8; nt++) {
            const int ch = nt * 8 + 2 * m4;
            stg[ch * 132 + q]             = oacc[mt][nt][0] * scl[mt][0];
            stg[(ch + 1) * 132 + q]       = oacc[mt][nt][1] * scl[mt][0];
            stg[ch * 132 + q + 8]         = oacc[mt][nt][2] * scl[mt][1];
            stg[(ch + 1) * 132 + q + 8]   = oacc[mt][nt][3] * scl[mt][1];
        }
    }
    __syncthreads();
    #pragma unroll
    for (int idx = tid; idx < 64 * 32; idx += 128) {
        const int ch = idx >> 5, q4 = idx & 31;
        float4 v = *(const float4*)&stg[ch * 132 + q4 * 4];
        const size_t g = (size_t)(z * CHPC + ch) * HW + q0 + q4 * 4;
        float4 s4 = *(const float4*)&sp[g];
        v.x += s4.x; v.y += s4.y; v.z += s4.z; v.w += s4.w;
        *(float4*)&op[g] = v;
    }
}

// ============================================================
extern "C" void kernel_launch(void* const* d_in, const int* in_sizes, int n_in,
                              void* d_out, int out_size)
{
    const float* src    = (const float*)d_in[0];
    const float* ref    = (const float*)d_in[1];
    const float* w_src  = (const float*)d_in[2];
    const float* b_src  = (const float*)d_in[3];
    const float* w_ref  = (const float*)d_in[4];
    const float* b_ref  = (const float*)d_in[5];
    const float* w_gate = (const float*)d_in[6];
    const float* b_gate = (const float*)d_in[7];
    const float* gamma  = (const float*)d_in[8];
    float* out = (float*)d_out;

    cudaFuncSetAttribute(attn_kernel, cudaFuncAttributeMaxDynamicSharedMemorySize,
                         SM_TOTAL);

    proj_kernel<<<dim3(HW / 256, NB, 6), 256>>>(src, ref, w_src, b_src,
                                                w_ref, b_ref, w_gate, b_gate);
    attn_kernel<<<dim3(HW / BQ, NB, 4), 128, SM_TOTAL>>>(src, gamma, out);
}

// round 10
// speedup vs baseline: 8.1486x; 1.5542x over previous
#include <cuda_runtime.h>
#include <cuda_bf16.h>
#include <cstdint>

#define HW   4096
#define NB   4
#define CIN  256
#define DQK  64
#define BQ   128          // queries per CTA (4 warps x 32 rows)
#define BK   64           // keys per iteration
#define NITER (HW / BK)   // 64
#define CHPC 64           // channels per CTA (z-split x4)

// (1/16) * log2(e), folded into Q at projection time
#define QSCL (0.0625f * 1.44269504088896f)
#define ONESB2 0x3F803F80u   /* bf16x2 {1.0, 1.0} */

// ---------------- scratch (bf16) ----------------
__device__ __nv_bfloat16 Qg[NB * HW * DQK];        // [b][i][k]   2 MB (pre-scaled)
__device__ __nv_bfloat16 Kg[NB * HW * DQK];        // [b][j][k]   2 MB
__device__ __nv_bfloat16 Vtg[NB * CIN * HW];       // [b][c][j]   8 MB (channel-major)

// ---------------- helpers ----------------
__device__ __forceinline__ uint32_t smem_u32(const void* p) {
    uint32_t a;
    asm("{ .reg .u64 t; cvta.to.shared.u64 t, %1; cvt.u32.u64 %0, t; }" : "=r"(a) : "l"(p));
    return a;
}
__device__ __forceinline__ void cp_async16(uint32_t dst, const void* src) {
    asm volatile("cp.async.cg.shared.global [%0], [%1], 16;" :: "r"(dst), "l"(src));
}
#define CP_COMMIT() asm volatile("cp.async.commit_group;" ::: "memory")

__device__ __forceinline__ uint32_t lds_b32(uint32_t a) {
    uint32_t v;
    asm volatile("ld.shared.b32 %0, [%1];" : "=r"(v) : "r"(a));
    return v;
}
__device__ __forceinline__ void ldmx4(uint32_t* r, uint32_t a) {
    asm volatile("ldmatrix.sync.aligned.m8n8.x4.shared.b16 {%0,%1,%2,%3}, [%4];"
                 : "=r"(r[0]), "=r"(r[1]), "=r"(r[2]), "=r"(r[3]) : "r"(a));
}
__device__ __forceinline__ uint32_t cvt_bf16x2(float lo, float hi) {
    uint32_t r;
    asm("cvt.rn.bf16x2.f32 %0, %1, %2;" : "=r"(r) : "f"(hi), "f"(lo));
    return r;
}
__device__ __forceinline__ uint32_t ex2_b2(uint32_t x) {
    uint32_t r;
    asm("ex2.approx.ftz.bf16x2 %0, %1;" : "=r"(r) : "r"(x));
    return r;
}
// D += A(16x16,row) * B(16x8,col)  bf16 -> f32
__device__ __forceinline__ void mma16816(float* c,
                                         uint32_t a0, uint32_t a1, uint32_t a2, uint32_t a3,
                                         uint32_t b0, uint32_t b1) {
    asm volatile(
        "mma.sync.aligned.m16n8k16.row.col.f32.bf16.bf16.f32 "
        "{%0,%1,%2,%3}, {%4,%5,%6,%7}, {%8,%9}, {%0,%1,%2,%3};"
        : "+f"(c[0]), "+f"(c[1]), "+f"(c[2]), "+f"(c[3])
        : "r"(a0), "r"(a1), "r"(a2), "r"(a3), "r"(b0), "r"(b1));
}
// D += A(16x8,row) * B(8x8,col)  tf32 -> f32
__device__ __forceinline__ void mma_tf32(float* c,
                                         uint32_t a0, uint32_t a1, uint32_t a2, uint32_t a3,
                                         uint32_t b0, uint32_t b1) {
    asm volatile(
        "mma.sync.aligned.m16n8k8.row.col.f32.tf32.tf32.f32 "
        "{%0,%1,%2,%3}, {%4,%5,%6,%7}, {%8,%9}, {%0,%1,%2,%3};"
        : "+f"(c[0]), "+f"(c[1]), "+f"(c[2]), "+f"(c[3])
        : "r"(a0), "r"(a1), "r"(a2), "r"(a3), "r"(b0), "r"(b1));
}

// ---------------- attn SMEM layout (bytes) ----------------
#define KROW    144
#define VROW    144
#define SM_Q    0                  // 128 x 144 = 18432
#define SM_K0   18432              // 64  x 144 =  9216
#define SM_K1   27648
#define SM_V0   36864              // 64  x 144 =  9216
#define SM_V1   46080
#define SM_TOTAL 55296
#define SM_STG  18432              // epilogue staging: 64*132*4 = 33792

// ---------------- proj SMEM layout (bytes) ----------------
#define XROWB 544                  // 128 fp32 + 32B pad
#define WROWB 272                  // 64 fp32 + 16B pad
#define PX0 0                      // 64 x 544 = 34816
#define PX1 34816
#define PW0 69632                  // 64 x 272 = 17408
#define PW1 87040
#define P_TOTAL 104448
#define PSTGROW 144                // Q/K transpose staging: 128 rows x 144B (in PX0)

// ============================================================
// Projection via tf32 tensor cores.
// grid (HW/128=32, NB, 6): z=0->Q (src,w_src), z=1->K (ref,w_ref),
//                          z=2..5 -> V chunk (ref, w_gate+(z-2)*64 rows)
// 128 threads, M=64 (1 m-tile per warp), N=128, K=256 in 4 chunks of 64
// (8 k-steps of 8 per chunk).
// ============================================================
__global__ __launch_bounds__(128, 2) void proj_tc(
    const float* __restrict__ src, const float* __restrict__ ref,
    const float* __restrict__ w_src, const float* __restrict__ b_src,
    const float* __restrict__ w_ref, const float* __restrict__ b_ref,
    const float* __restrict__ w_gate, const float* __restrict__ b_gate)
{
    extern __shared__ char smem[];
    const uint32_t sb = smem_u32(smem);
    const int tid  = threadIdx.x;
    const int warp = tid >> 5;
    const int lane = tid & 31;
    const int row4 = lane >> 2;     // 0..7
    const int q4   = lane & 3;      // 0..3
    const int z    = blockIdx.z;
    const int b    = blockIdx.y;
    const int i0   = blockIdx.x * 128;

    const float *X, *W, *bias;
    if (z == 0)      { X = src; W = w_src;                       bias = b_src; }
    else if (z == 1) { X = ref; W = w_ref;                       bias = b_ref; }
    else             { X = ref; W = w_gate + (z - 2) * 64 * CIN; bias = b_gate + (z - 2) * 64; }
    const float* Xb = X + (size_t)b * CIN * HW;

    // ---- cp.async chunk loader: X [64 c][128 i] fp32, W [64 o][64 c] fp32 ----
    auto issue_chunk = [&](int kc, int buf) {
        const uint32_t xb = sb + (buf ? PX1 : PX0);
        const uint32_t wb = sb + (buf ? PW1 : PW0);
        #pragma unroll
        for (int t = tid; t < 64 * 32; t += 128) {
            int r = t >> 5, s = t & 31;
            cp_async16(xb + r * XROWB + s * 16, Xb + (size_t)(kc * 64 + r) * HW + i0 + s * 4);
        }
        #pragma unroll
        for (int t = tid; t < 64 * 16; t += 128) {
            int r = t >> 4, s = t & 15;
            cp_async16(wb + r * WROWB + s * 16, W + r * CIN + kc * 64 + s * 4);
        }
    };

    issue_chunk(0, 0);
    CP_COMMIT();

    float acc[16][4];
    #pragma unroll
    for (int nt = 0; nt < 16; nt++)
        #pragma unroll
        for (int c = 0; c < 4; c++) acc[nt][c] = 0.f;

    #pragma unroll 1
    for (int kc = 0; kc < 4; kc++) {
        if (kc + 1 < 4) {
            issue_chunk(kc + 1, (kc + 1) & 1);
            CP_COMMIT();
            asm volatile("cp.async.wait_group 1;" ::: "memory");
        } else {
            asm volatile("cp.async.wait_group 0;" ::: "memory");
        }
        __syncthreads();

        const uint32_t xb = sb + ((kc & 1) ? PX1 : PX0);
        const uint32_t wb = sb + ((kc & 1) ? PW1 : PW0);
        const uint32_t abase = wb + (warp * 16 + row4) * WROWB + q4 * 4;
        const uint32_t bbase = xb + q4 * XROWB + row4 * 4;

        // 8 k-steps of k=8 cover this 64-wide K chunk
        #pragma unroll
        for (int ks = 0; ks < 8; ks++) {
            uint32_t a0 = lds_b32(abase + ks * 32);
            uint32_t a1 = lds_b32(abase + 8 * WROWB + ks * 32);
            uint32_t a2 = lds_b32(abase + ks * 32 + 16);
            uint32_t a3 = lds_b32(abase + 8 * WROWB + ks * 32 + 16);
            const uint32_t bk = bbase + ks * 8 * XROWB;
            #pragma unroll
            for (int nt = 0; nt < 16; nt++) {
                uint32_t b0 = lds_b32(bk + nt * 32);
                uint32_t b1 = lds_b32(bk + 4 * XROWB + nt * 32);
                mma_tf32(acc[nt], a0, a1, a2, a3, b0, b1);
            }
        }
        __syncthreads();
    }

    // ---- epilogue ----
    const int olo = warp * 16 + row4;      // local out-channel (0..63)
    const float bv0 = bias[olo];
    const float bv8 = bias[olo + 8];

    if (z >= 2) {
        // V: write directly to Vtg [channel][i], bf16x2 packed
        const int ch0 = (z - 2) * 64;
        #pragma unroll
        for (int nt = 0; nt < 16; nt++) {
            const int i = i0 + nt * 8 + 2 * q4;
            *(uint32_t*)(Vtg + ((size_t)(b * CIN + ch0 + olo)) * HW + i) =
                cvt_bf16x2(acc[nt][0] + bv0, acc[nt][1] + bv0);
            *(uint32_t*)(Vtg + ((size_t)(b * CIN + ch0 + olo + 8)) * HW + i) =
                cvt_bf16x2(acc[nt][2] + bv8, acc[nt][3] + bv8);
        }
    } else {
        // Q/K: transpose via smem staging [i][o] (reuses PX0; last compute used PX1/PW1)
        const float s = (z == 0) ? QSCL : 1.0f;
        __nv_bfloat16* stg = (__nv_bfloat16*)smem;
        #pragma unroll
        for (int nt = 0; nt < 16; nt++) {
            const int i = nt * 8 + 2 * q4;
            __nv_bfloat16* r0 = stg + (size_t)i * (PSTGROW / 2);
            r0[olo]     = __float2bfloat16((acc[nt][0] + bv0) * s);
            r0[olo + 8] = __float2bfloat16((acc[nt][2] + bv8) * s);
            __nv_bfloat16* r1 = stg + (size_t)(i + 1) * (PSTGROW / 2);
            r1[olo]     = __float2bfloat16((acc[nt][1] + bv0) * s);
            r1[olo + 8] = __float2bfloat16((acc[nt][3] + bv8) * s);
        }
        __syncthreads();
        __nv_bfloat16* outp = (z == 0 ? Qg : Kg) + ((size_t)b * HW + i0) * DQK;
        #pragma unroll
        for (int t = tid; t < 1024; t += 128) {
            int r = t >> 3, seg = t & 7;
            *(uint4*)(outp + (size_t)r * DQK + seg * 8) =
                *(uint4*)((char*)smem + r * PSTGROW + seg * 16);
        }
    }
}

// ============================================================
// bf16 HMMA flash attention + epilogue. (unchanged from round 8)
// grid (HW/BQ=32, NB, 4): z selects 64 output channels.
// ============================================================
__device__ __forceinline__ void issue_kv(uint32_t sb, int koff, int voff,
                                         int b, int z, int j0, int tid)
{
    const __nv_bfloat16* kp = Kg + ((size_t)b * HW + j0) * DQK;
    #pragma unroll
    for (int t = tid; t < 64 * 8; t += 128) {
        int r = t >> 3, c8 = t & 7;
        cp_async16(sb + koff + r * KROW + c8 * 16, kp + r * DQK + c8 * 8);
    }
    #pragma unroll
    for (int t = tid; t < 64 * 8; t += 128) {
        int c = t >> 3, c8 = t & 7;
        cp_async16(sb + voff + c * VROW + c8 * 16,
                   Vtg + ((size_t)(b * CIN + z * CHPC + c)) * HW + j0 + c8 * 8);
    }
}

__global__ __launch_bounds__(128, 3) void attn_kernel(
    const float* __restrict__ srcf, const float* __restrict__ gammap,
    float* __restrict__ out)
{
    extern __shared__ char smem[];
    const uint32_t sb = smem_u32(smem);
    const int tid  = threadIdx.x;
    const int warp = tid >> 5;
    const int lane = tid & 31;
    const int b    = blockIdx.y;
    const int z    = blockIdx.z;
    const int q0   = blockIdx.x * BQ;
    const int qr   = (lane >> 2);
    const int m4   = (lane & 3);

    const uint32_t lmoff = (uint32_t)((((lane >> 4) & 1) * 8 + (lane & 7)) * KROW
                                      + ((lane >> 3) & 1) * 16);

    {
        const __nv_bfloat16* qp = Qg + ((size_t)b * HW + q0) * DQK;
        #pragma unroll
        for (int t = tid; t < 128 * 8; t += 128) {
            int r = t >> 3, c8 = t & 7;
            cp_async16(sb + SM_Q + r * KROW + c8 * 16, qp + r * DQK + c8 * 8);
        }
        CP_COMMIT();
        issue_kv(sb, SM_K0, SM_V0, b, z, 0, tid);
        CP_COMMIT();
    }

    uint32_t aq[2][4][4];
    {
        asm volatile("cp.async.wait_group 1;" ::: "memory");
        __syncthreads();
        #pragma unroll
        for (int mt = 0; mt < 2; mt++) {
            const uint32_t qbase = sb + SM_Q + (warp * 32 + mt * 16 + qr) * KROW + m4 * 4;
            #pragma unroll
            for (int ks = 0; ks < 4; ks++) {
                aq[mt][ks][0] = lds_b32(qbase + ks * 32);
                aq[mt][ks][1] = lds_b32(qbase + 8 * KROW + ks * 32);
                aq[mt][ks][2] = lds_b32(qbase + ks * 32 + 16);
                aq[mt][ks][3] = lds_b32(qbase + 8 * KROW + ks * 32 + 16);
            }
        }
    }

    float oacc[2][8][4];
    #pragma unroll
    for (int mt = 0; mt < 2; mt++)
        #pragma unroll
        for (int nt = 0; nt < 8; nt++)
            #pragma unroll
            for (int c = 0; c < 4; c++) oacc[mt][nt][c] = 0.f;
    float dden[2][4];
    #pragma unroll
    for (int mt = 0; mt < 2; mt++)
        #pragma unroll
        for (int c = 0; c < 4; c++) dden[mt][c] = 0.f;

    #pragma unroll 1
    for (int j = 0; j < NITER; j++) {
        const int koff = (j & 1) ? SM_K1 : SM_K0;
        const int voff = (j & 1) ? SM_V1 : SM_V0;

        if (j + 1 < NITER) {
            issue_kv(sb, (j & 1) ? SM_K0 : SM_K1, (j & 1) ? SM_V0 : SM_V1,
                     b, z, (j + 1) * BK, tid);
            CP_COMMIT();
            asm volatile("cp.async.wait_group 1;" ::: "memory");
        } else {
            asm volatile("cp.async.wait_group 0;" ::: "memory");
        }
        __syncthreads();

        const uint32_t kbase = sb + koff + lmoff;
        const uint32_t vbase = sb + voff + lmoff;

        #pragma unroll
        for (int tp = 0; tp < 4; tp++) {
            uint32_t kf[4][4];
            #pragma unroll
            for (int ks = 0; ks < 4; ks++)
                ldmx4(kf[ks], kbase + tp * (16 * KROW) + ks * 32);

            float s[2][2][4];
            #pragma unroll
            for (int mt = 0; mt < 2; mt++)
                #pragma unroll
                for (int nh = 0; nh < 2; nh++)
                    #pragma unroll
                    for (int c = 0; c < 4; c++) s[mt][nh][c] = 0.f;
            #pragma unroll
            for (int ks = 0; ks < 4; ks++)
                #pragma unroll
                for (int mt = 0; mt < 2; mt++) {
                    mma16816(s[mt][0], aq[mt][ks][0], aq[mt][ks][1],
                             aq[mt][ks][2], aq[mt][ks][3], kf[ks][0], kf[ks][1]);
                    mma16816(s[mt][1], aq[mt][ks][0], aq[mt][ks][1],
                             aq[mt][ks][2], aq[mt][ks][3], kf[ks][2], kf[ks][3]);
                }

            uint32_t pa[2][4];
            #pragma unroll
            for (int mt = 0; mt < 2; mt++) {
                pa[mt][0] = ex2_b2(cvt_bf16x2(s[mt][0][0], s[mt][0][1]));
                pa[mt][1] = ex2_b2(cvt_bf16x2(s[mt][0][2], s[mt][0][3]));
                pa[mt][2] = ex2_b2(cvt_bf16x2(s[mt][1][0], s[mt][1][1]));
                pa[mt][3] = ex2_b2(cvt_bf16x2(s[mt][1][2], s[mt][1][3]));
                mma16816(dden[mt], pa[mt][0], pa[mt][1], pa[mt][2], pa[mt][3],
                         ONESB2, ONESB2);
            }

            #pragma unroll
            for (int ntp = 0; ntp < 4; ntp++) {
                uint32_t vf[4];
                ldmx4(vf, vbase + tp * 32 + ntp * (16 * VROW));
                #pragma unroll
                for (int mt = 0; mt < 2; mt++) {
                    mma16816(oacc[mt][2 * ntp],     pa[mt][0], pa[mt][1],
                             pa[mt][2], pa[mt][3], vf[0], vf[1]);
                    mma16816(oacc[mt][2 * ntp + 1], pa[mt][0], pa[mt][1],
                             pa[mt][2], pa[mt][3], vf[2], vf[3]);
                }
            }
        }
        __syncthreads();
    }

    const float gamma = __ldg(gammap);
    float scl[2][2];
    #pragma unroll
    for (int mt = 0; mt < 2; mt++) {
        scl[mt][0] = gamma / dden[mt][0];
        scl[mt][1] = gamma / dden[mt][2];
    }

    float* stg = (float*)(smem + SM_STG);
    const float* sp = srcf + (size_t)b * CIN * HW;
    float*       op = out  + (size_t)b * CIN * HW;

    #pragma unroll
    for (int mt = 0; mt < 2; mt++) {
        const int q = warp * 32 + mt * 16 + qr;
        #pragma unroll
        for (int nt = 0; nt < 8; nt++) {
            const int ch = nt * 8 + 2 * m4;
            stg[ch * 132 + q]             = oacc[mt][nt][0] * scl[mt][0];
            stg[(ch + 1) * 132 + q]       = oacc[mt][nt][1] * scl[mt][0];
            stg[ch * 132 + q + 8]         = oacc[mt][nt][2] * scl[mt][1];
            stg[(ch + 1) * 132 + q + 8]   = oacc[mt][nt][3] * scl[mt][1];
        }
    }
    __syncthreads();
    #pragma unroll
    for (int idx = tid; idx < 64 * 32; idx += 128) {
        const int ch = idx >> 5, q4 = idx & 31;
        float4 v = *(const float4*)&stg[ch * 132 + q4 * 4];
        const size_t g = (size_t)(z * CHPC + ch) * HW + q0 + q4 * 4;
        float4 s4 = *(const float4*)&sp[g];
        v.x += s4.x; v.y += s4.y; v.z += s4.z; v.w += s4.w;
        *(float4*)&op[g] = v;
    }
}

// ============================================================
extern "C" void kernel_launch(void* const* d_in, const int* in_sizes, int n_in,
                              void* d_out, int out_size)
{
    const float* src    = (const float*)d_in[0];
    const float* ref    = (const float*)d_in[1];
    const float* w_src  = (const float*)d_in[2];
    const float* b_src  = (const float*)d_in[3];
    const float* w_ref  = (const float*)d_in[4];
    const float* b_ref  = (const float*)d_in[5];
    const float* w_gate = (const float*)d_in[6];
    const float* b_gate = (const float*)d_in[7];
    const float* gamma  = (const float*)d_in[8];
    float* out = (float*)d_out;

    cudaFuncSetAttribute(proj_tc, cudaFuncAttributeMaxDynamicSharedMemorySize, P_TOTAL);
    cudaFuncSetAttribute(attn_kernel, cudaFuncAttributeMaxDynamicSharedMemorySize, SM_TOTAL);

    proj_tc<<<dim3(HW / 128, NB, 6), 128, P_TOTAL>>>(src, ref, w_src, b_src,
                                                     w_ref, b_ref, w_gate, b_gate);
    attn_kernel<<<dim3(HW / BQ, NB, 4), 128, SM_TOTAL>>>(src, gamma, out);
}